// round 16
// baseline (speedup 1.0000x reference)
#include <cuda_runtime.h>
#include <stdint.h>

#define NROWS   (64*2048)
#define DIM     64
#define KC      1024
#define QELEMS  (NROWS*DIM)
#define BT      256
#define RWS     64                 // rows per CTA
#define CKT     64                 // codes per tile
#define NTL     (KC/CKT)           // 16 tiles
#define TB      (CKT*DIM*4)        // 16 KB per code tile

// dynamic smem offsets (bytes)
#define SM_X    0                   // x tile [k2p][row][16B]: 16 KB
#define SM_C    16384               // code tiles x2 [k2p][code][16B]: 32 KB
#define SM_SS   49152               // float ssv[1024]
#define SM_C4   53248               // float c4v[64]
#define SM_RV   53504               // float resV[64]
#define SM_RI   53760               // int resI[64]
#define SM_RED  54016               // double sred[2]
#define SMEMSZ  54144

__device__ double g_loss_acc;
__device__ int    g_ctr;
__device__ float  g_ssb[KC];

static __device__ __forceinline__ unsigned long long ffma2(unsigned long long a,
                                                           unsigned long long b,
                                                           unsigned long long c){
    unsigned long long r;
    asm("fma.rn.f32x2 %0, %1, %2, %3;" : "=l"(r) : "l"(a), "l"(b), "l"(c));
    return r;
}
static __device__ __forceinline__ void unpack2(unsigned long long v, float& a, float& b){
    asm("mov.b64 {%0,%1}, %2;" : "=f"(a), "=f"(b) : "l"(v));
}
static __device__ __forceinline__ void cp16(uint32_t dst, const void* src){
    asm volatile("cp.async.cg.shared.global [%0], [%1], 16;" :: "r"(dst), "l"(src));
}

// prep: exact sequential code norms (reference rounding order), once
__global__ void vq_prep(const float* __restrict__ w){
    int code = blockIdx.x*blockDim.x + threadIdx.x;   // 1024 threads
    const float4* wr = reinterpret_cast<const float4*>(w + (size_t)code*DIM);
    float s = 0.f;
    #pragma unroll
    for (int i=0;i<16;i++){
        float4 v = wr[i];
        s = __fadd_rn(s, __fmul_rn(v.x,v.x));
        s = __fadd_rn(s, __fmul_rn(v.y,v.y));
        s = __fadd_rn(s, __fmul_rn(v.z,v.z));
        s = __fadd_rn(s, __fmul_rn(v.w,v.w));
    }
    g_ssb[code] = s;
}

__global__ __launch_bounds__(BT, 3) void vq_main(const float* __restrict__ x,
                                                 const float* __restrict__ w,
                                                 float* __restrict__ out)
{
    extern __shared__ char sm[];
    float*  ssv  = reinterpret_cast<float*>(sm + SM_SS);
    float*  c4v  = reinterpret_cast<float*>(sm + SM_C4);
    float*  resV = reinterpret_cast<float*>(sm + SM_RV);
    int*    resI = reinterpret_cast<int*>(sm + SM_RI);
    double* sred = reinterpret_cast<double*>(sm + SM_RED);
    const ulonglong2* XS = reinterpret_cast<const ulonglong2*>(sm + SM_X);
    const ulonglong2* CS = reinterpret_cast<const ulonglong2*>(sm + SM_C);

    const int tid = threadIdx.x;
    const int j   = tid & 7;           // code group 0..7
    const int i   = tid >> 3;          // row group 0..31
    const size_t base = (size_t)blockIdx.x * RWS;

    const uint32_t smb = (uint32_t)__cvta_generic_to_shared(sm);
    const uint32_t smx = smb + SM_X;
    const uint32_t smc = smb + SM_C;

    // ---- async x tile: 1024 chunks; m -> (r=m&63, g=m>>6); dst [g][r][16B] ----
    {
        const char* xs = (const char*)x + base*DIM*4;
        #pragma unroll
        for (int q=0;q<4;q++){
            int m = tid + q*BT;
            int r = m & 63, g = m >> 6;
            cp16(smx + (uint32_t)(g*1024 + r*16), xs + (size_t)r*256 + g*16);
        }
        asm volatile("cp.async.commit_group;");
    }
    // ---- async code tile 0 ----
    #pragma unroll
    for (int q=0;q<4;q++){
        int m = tid + q*BT;
        int c = m & 63, g = m >> 6;
        cp16(smc + (uint32_t)(g*1024 + c*16), (const char*)w + (size_t)c*256 + g*16);
    }
    asm volatile("cp.async.commit_group;");

    // ---- norms to smem ----
    #pragma unroll
    for (int k=0;k<KC/BT;k++) ssv[tid + k*BT] = g_ssb[tid + k*BT];
    if (tid < RWS){
        const float4* xr = reinterpret_cast<const float4*>(x + (base + tid)*DIM);
        float s = 0.f;
        #pragma unroll
        for (int q=0;q<16;q++){
            float4 v = xr[q];
            s = __fadd_rn(s, __fmul_rn(v.x,v.x));
            s = __fadd_rn(s, __fmul_rn(v.y,v.y));
            s = __fadd_rn(s, __fmul_rn(v.z,v.z));
            s = __fadd_rn(s, __fmul_rn(v.w,v.w));
        }
        c4v[tid] = s;
    }

    float minv[2] = {3.4e38f,3.4e38f};
    int   mini[2] = {0,0};
    float c4r[2];
    bool c4ld = false;

    #pragma unroll 1
    for (int t=0; t<NTL; t++){
        if (t+1 < NTL){
            const char* srcb = (const char*)w + (size_t)(t+1)*TB;
            uint32_t dstb = smc + (uint32_t)(((t+1)&1)*TB);
            #pragma unroll
            for (int q=0;q<4;q++){
                int m = tid + q*BT;
                int c = m & 63, g = m >> 6;
                cp16(dstb + (uint32_t)(g*1024 + c*16), srcb + (size_t)c*256 + g*16);
            }
            asm volatile("cp.async.commit_group;");
            asm volatile("cp.async.wait_group 1;");
        } else {
            asm volatile("cp.async.wait_group 0;");
        }
        __syncthreads();
        if (!c4ld){
            c4ld = true;
            c4r[0] = c4v[i];
            c4r[1] = c4v[i + 32];
        }

        const ulonglong2* Ct = CS + (t&1)*(TB/16);
        unsigned long long acc[16];
        #pragma unroll
        for (int q=0;q<16;q++) acc[q] = 0ull;

        #pragma unroll 4
        for (int p=0;p<16;p++){                 // k2-pair: dims 4p..4p+3
            ulonglong2 rA[2], cA[4];
            rA[0] = XS[p*64 + i];
            rA[1] = XS[p*64 + i + 32];
            // half 1: codes r=0..3
            #pragma unroll
            for (int r=0;r<4;r++) cA[r] = Ct[p*64 + j + 8*r];
            #pragma unroll
            for (int s=0;s<2;s++){
                #pragma unroll
                for (int r=0;r<4;r++){
                    acc[s*8+r] = ffma2(rA[s].x, cA[r].x, acc[s*8+r]);
                    acc[s*8+r] = ffma2(rA[s].y, cA[r].y, acc[s*8+r]);
                }
            }
            // half 2: codes r=4..7 (reuse cA registers)
            #pragma unroll
            for (int r=0;r<4;r++) cA[r] = Ct[p*64 + j + 8*(r+4)];
            #pragma unroll
            for (int s=0;s<2;s++){
                #pragma unroll
                for (int r=0;r<4;r++){
                    acc[s*8+r+4] = ffma2(rA[s].x, cA[r].x, acc[s*8+r+4]);
                    acc[s*8+r+4] = ffma2(rA[s].y, cA[r].y, acc[s*8+r+4]);
                }
            }
        }

        // tail: 16 dots; codes ascend in r for first-min semantics
        float ssq[8];
        #pragma unroll
        for (int r=0;r<8;r++) ssq[r] = ssv[t*CKT + 8*r + j];
        #pragma unroll
        for (int s=0;s<2;s++){
            #pragma unroll
            for (int r=0;r<8;r++){
                float lo, hi;
                unpack2(acc[s*8+r], lo, hi);
                float m  = __fadd_rn(lo, hi);
                float dv = __fmaf_rn(m, -2.0f, __fadd_rn(c4r[s], ssq[r]));
                int  idx = t*CKT + 8*r + j;
                if (dv < minv[s]){ minv[s] = dv; mini[s] = idx; }
            }
        }
        __syncthreads();
    }

    // ---- cross-j reduce (8-lane groups), lexicographic (dv, idx) ----
    #pragma unroll
    for (int off=1; off<8; off<<=1){
        #pragma unroll
        for (int s=0;s<2;s++){
            float od = __shfl_xor_sync(0xffffffffu, minv[s], off);
            int   oi = __shfl_xor_sync(0xffffffffu, mini[s], off);
            if (od < minv[s] || (od == minv[s] && oi < mini[s])){
                minv[s] = od; mini[s] = oi;
            }
        }
    }
    if (j == 0){
        #pragma unroll
        for (int s=0;s<2;s++){ resV[i + 32*s] = minv[s]; resI[i + 32*s] = mini[s]; }
    }
    __syncthreads();

    // ---- loss partial (rows 0..63 by first 64 threads) ----
    if (tid < RWS){
        double v = (double)resV[tid];
        #pragma unroll
        for (int o=16;o>0;o>>=1) v += __shfl_down_sync(0xffffffffu, v, o);
        if ((tid & 31) == 0) sred[tid>>5] = v;
    }
    __syncthreads();
    if (tid == 0){
        atomicAdd(&g_loss_acc, sred[0] + sred[1]);
        __threadfence();
        int done = atomicAdd(&g_ctr, 1);
        if (done == (int)gridDim.x - 1){
            double tot = atomicAdd(&g_loss_acc, 0.0);
            out[0] = (float)(tot*1.25/(double)QELEMS);
            g_ctr = 0;
            g_loss_acc = 0.0;
        }
    }

    // ---- epilogue: indices + straight-through rows (4 threads/row) ----
    {
        int rloc = tid >> 2;                 // row 0..63
        int c    = tid & 3;                  // 16-dim chunk
        size_t grow = base + rloc;
        int idx = resI[rloc];
        if (c == 0) out[1 + QELEMS + grow] = (float)idx;

        const float4* qw = reinterpret_cast<const float4*>(w + (size_t)idx*DIM + c*16);
        const float4* xr = reinterpret_cast<const float4*>(x + grow*DIM + c*16);
        float stq[16];
        #pragma unroll
        for (int q=0;q<4;q++){
            float4 qv = qw[q];
            float4 xv = xr[q];
            stq[4*q+0] = __fadd_rn(xv.x, __fsub_rn(qv.x, xv.x));
            stq[4*q+1] = __fadd_rn(xv.y, __fsub_rn(qv.y, xv.y));
            stq[4*q+2] = __fadd_rn(xv.z, __fsub_rn(qv.z, xv.z));
            stq[4*q+3] = __fadd_rn(xv.w, __fsub_rn(qv.w, xv.w));
        }
        // out+1 is 4B-aligned: 3 scalars, 3 float4, 1 scalar per 16-chunk
        float* og = out + 1 + grow*DIM + c*16;
        og[0]=stq[0]; og[1]=stq[1]; og[2]=stq[2];
        float4* ov = reinterpret_cast<float4*>(og + 3);
        #pragma unroll
        for (int q=0;q<3;q++){
            float4 r;
            r.x=stq[3+4*q]; r.y=stq[4+4*q]; r.z=stq[5+4*q]; r.w=stq[6+4*q];
            ov[q] = r;
        }
        og[15]=stq[15];
    }
}

extern "C" void kernel_launch(void* const* d_in, const int* in_sizes, int n_in,
                              void* d_out, int out_size)
{
    const float* x  = (const float*)d_in[0];
    const float* wt = (const float*)d_in[1];
    float* out = (float*)d_out;

    cudaFuncSetAttribute(vq_main, cudaFuncAttributeMaxDynamicSharedMemorySize, SMEMSZ);

    vq_prep<<<KC/BT, BT>>>(wt);
    vq_main<<<NROWS/RWS, BT, SMEMSZ>>>(x, wt, out);
}

// round 17
// speedup vs baseline: 1.4758x; 1.4758x over previous
#include <cuda_runtime.h>
#include <stdint.h>

#define NROWS   (64*2048)
#define DIM     64
#define KC      1024
#define QELEMS  (NROWS*DIM)
#define BT      256
#define RWS     128                // rows per CTA
#define CKT     64                 // codes per tile
#define NTL     (KC/CKT)           // 16 tiles
#define TB      (CKT*DIM*4)        // 16 KB per code tile

// dynamic smem offsets (bytes)
#define SM_X    0                   // x tile [k2p][row][16B]: 32 KB
#define SM_C    32768               // code tiles x2 [k2p][code][16B]: 32 KB
#define SM_SS   65536               // float ssv[1024]
#define SM_C4   69632               // float c4v[128]
#define SM_RV   70144               // float resV[128]
#define SM_RI   70656               // int resI[128]
#define SM_RED  71168               // double sred[4]
#define SMEMSZ  71232

__device__ double g_loss_acc;
__device__ int    g_ctr;
__device__ float  g_ssb[KC];

static __device__ __forceinline__ unsigned long long ffma2(unsigned long long a,
                                                           unsigned long long b,
                                                           unsigned long long c){
    unsigned long long r;
    asm("fma.rn.f32x2 %0, %1, %2, %3;" : "=l"(r) : "l"(a), "l"(b), "l"(c));
    return r;
}
static __device__ __forceinline__ void unpack2(unsigned long long v, float& a, float& b){
    asm("mov.b64 {%0,%1}, %2;" : "=f"(a), "=f"(b) : "l"(v));
}
static __device__ __forceinline__ void cp16(uint32_t dst, const void* src){
    asm volatile("cp.async.cg.shared.global [%0], [%1], 16;" :: "r"(dst), "l"(src));
}

// prep: exact sequential code norms (reference rounding order), once
__global__ void vq_prep(const float* __restrict__ w){
    int code = blockIdx.x*blockDim.x + threadIdx.x;   // 1024 threads
    const float4* wr = reinterpret_cast<const float4*>(w + (size_t)code*DIM);
    float s = 0.f;
    #pragma unroll
    for (int i=0;i<16;i++){
        float4 v = wr[i];
        s = __fadd_rn(s, __fmul_rn(v.x,v.x));
        s = __fadd_rn(s, __fmul_rn(v.y,v.y));
        s = __fadd_rn(s, __fmul_rn(v.z,v.z));
        s = __fadd_rn(s, __fmul_rn(v.w,v.w));
    }
    g_ssb[code] = s;
}

__global__ __launch_bounds__(BT, 2) void vq_main(const float* __restrict__ x,
                                                 const float* __restrict__ w,
                                                 float* __restrict__ out)
{
    extern __shared__ char sm[];
    float*  ssv  = reinterpret_cast<float*>(sm + SM_SS);
    float*  c4v  = reinterpret_cast<float*>(sm + SM_C4);
    float*  resV = reinterpret_cast<float*>(sm + SM_RV);
    int*    resI = reinterpret_cast<int*>(sm + SM_RI);
    double* sred = reinterpret_cast<double*>(sm + SM_RED);
    const ulonglong2* XS = reinterpret_cast<const ulonglong2*>(sm + SM_X);
    const ulonglong2* CS = reinterpret_cast<const ulonglong2*>(sm + SM_C);

    const int tid = threadIdx.x;
    const int j   = tid & 7;           // code group 0..7
    const int i   = tid >> 3;          // row group 0..31
    const size_t base = (size_t)blockIdx.x * RWS;

    const uint32_t smb = (uint32_t)__cvta_generic_to_shared(sm);
    const uint32_t smx = smb + SM_X;
    const uint32_t smc = smb + SM_C;

    // ---- async x tile: 2048 chunks; m -> (r=m&127, g=m>>7); dst [g][r][16B] ----
    {
        const char* xs = (const char*)x + base*DIM*4;
        #pragma unroll
        for (int q=0;q<8;q++){
            int m = tid + q*BT;
            int r = m & 127, g = m >> 7;
            cp16(smx + (uint32_t)(g*2048 + r*16), xs + (size_t)r*256 + g*16);
        }
        asm volatile("cp.async.commit_group;");
    }
    // ---- async code tile 0 ----
    #pragma unroll
    for (int q=0;q<4;q++){
        int m = tid + q*BT;
        int c = m & 63, g = m >> 6;
        cp16(smc + (uint32_t)(g*1024 + c*16), (const char*)w + (size_t)c*256 + g*16);
    }
    asm volatile("cp.async.commit_group;");

    // ---- norms to smem ----
    #pragma unroll
    for (int k=0;k<KC/BT;k++) ssv[tid + k*BT] = g_ssb[tid + k*BT];
    if (tid < RWS){
        const float4* xr = reinterpret_cast<const float4*>(x + (base + tid)*DIM);
        float s = 0.f;
        #pragma unroll
        for (int q=0;q<16;q++){
            float4 v = xr[q];
            s = __fadd_rn(s, __fmul_rn(v.x,v.x));
            s = __fadd_rn(s, __fmul_rn(v.y,v.y));
            s = __fadd_rn(s, __fmul_rn(v.z,v.z));
            s = __fadd_rn(s, __fmul_rn(v.w,v.w));
        }
        c4v[tid] = s;
    }

    float minv[4] = {3.4e38f,3.4e38f,3.4e38f,3.4e38f};
    int   mini[4] = {0,0,0,0};
    float c4r[4];
    bool c4ld = false;

    #pragma unroll 1
    for (int t=0; t<NTL; t++){
        if (t+1 < NTL){
            const char* srcb = (const char*)w + (size_t)(t+1)*TB;
            uint32_t dstb = smc + (uint32_t)(((t+1)&1)*TB);
            #pragma unroll
            for (int q=0;q<4;q++){
                int m = tid + q*BT;
                int c = m & 63, g = m >> 6;
                cp16(dstb + (uint32_t)(g*1024 + c*16), srcb + (size_t)c*256 + g*16);
            }
            asm volatile("cp.async.commit_group;");
            asm volatile("cp.async.wait_group 1;");
        } else {
            asm volatile("cp.async.wait_group 0;");
        }
        __syncthreads();
        if (!c4ld){
            c4ld = true;
            #pragma unroll
            for (int s=0;s<4;s++) c4r[s] = c4v[i + 32*s];
        }

        const ulonglong2* Ct = CS + (t&1)*(TB/16);
        unsigned long long acc[32];
        #pragma unroll
        for (int q=0;q<32;q++) acc[q] = 0ull;

        #pragma unroll
        for (int p=0;p<16;p++){                 // k2-pair: dims 4p..4p+3 (FULL unroll)
            // half 1: rA + codes r=0..3
            ulonglong2 rA[4], cA[4];
            #pragma unroll
            for (int s=0;s<4;s++) rA[s] = XS[p*128 + i + 32*s];
            #pragma unroll
            for (int r=0;r<4;r++) cA[r] = Ct[p*64 + j + 8*r];
            #pragma unroll
            for (int s=0;s<4;s++){
                #pragma unroll
                for (int r=0;r<4;r++){
                    acc[s*8+r] = ffma2(rA[s].x, cA[r].x, acc[s*8+r]);
                    acc[s*8+r] = ffma2(rA[s].y, cA[r].y, acc[s*8+r]);
                }
            }
            // half 2: codes r=4..7 (reuse cA registers)
            #pragma unroll
            for (int r=0;r<4;r++) cA[r] = Ct[p*64 + j + 8*(r+4)];
            #pragma unroll
            for (int s=0;s<4;s++){
                #pragma unroll
                for (int r=0;r<4;r++){
                    acc[s*8+r+4] = ffma2(rA[s].x, cA[r].x, acc[s*8+r+4]);
                    acc[s*8+r+4] = ffma2(rA[s].y, cA[r].y, acc[s*8+r+4]);
                }
            }
        }

        // tail: 32 dots; codes ascend in r for first-min semantics
        float ssq[8];
        #pragma unroll
        for (int r=0;r<8;r++) ssq[r] = ssv[t*CKT + 8*r + j];
        #pragma unroll
        for (int s=0;s<4;s++){
            #pragma unroll
            for (int r=0;r<8;r++){
                float lo, hi;
                unpack2(acc[s*8+r], lo, hi);
                float m  = __fadd_rn(lo, hi);
                float dv = __fmaf_rn(m, -2.0f, __fadd_rn(c4r[s], ssq[r]));
                int  idx = t*CKT + 8*r + j;
                if (dv < minv[s]){ minv[s] = dv; mini[s] = idx; }
            }
        }
        __syncthreads();
    }

    // ---- cross-j reduce (8-lane groups), lexicographic (dv, idx) ----
    #pragma unroll
    for (int off=1; off<8; off<<=1){
        #pragma unroll
        for (int s=0;s<4;s++){
            float od = __shfl_xor_sync(0xffffffffu, minv[s], off);
            int   oi = __shfl_xor_sync(0xffffffffu, mini[s], off);
            if (od < minv[s] || (od == minv[s] && oi < mini[s])){
                minv[s] = od; mini[s] = oi;
            }
        }
    }
    if (j == 0){
        #pragma unroll
        for (int s=0;s<4;s++){ resV[i + 32*s] = minv[s]; resI[i + 32*s] = mini[s]; }
    }
    __syncthreads();

    // ---- loss partial (rows 0..127 by first 128 threads) ----
    if (tid < RWS){
        double v = (double)resV[tid];
        #pragma unroll
        for (int o=16;o>0;o>>=1) v += __shfl_down_sync(0xffffffffu, v, o);
        if ((tid & 31) == 0) sred[tid>>5] = v;
    }
    __syncthreads();
    if (tid == 0){
        atomicAdd(&g_loss_acc, sred[0] + sred[1] + sred[2] + sred[3]);
        __threadfence();
        int done = atomicAdd(&g_ctr, 1);
        if (done == (int)gridDim.x - 1){
            double tot = atomicAdd(&g_loss_acc, 0.0);
            out[0] = (float)(tot*1.25/(double)QELEMS);
            g_ctr = 0;
            g_loss_acc = 0.0;
        }
    }

    // ---- epilogue: indices + straight-through rows (2 threads/row, 32B each) ----
    {
        int rloc = tid >> 1;                 // row 0..127
        int c    = tid & 1;                  // 32-dim half
        size_t grow = base + rloc;
        int idx = resI[rloc];
        if (c == 0) out[1 + QELEMS + grow] = (float)idx;

        const float4* qw = reinterpret_cast<const float4*>(w + (size_t)idx*DIM + c*32);
        const float4* xr = reinterpret_cast<const float4*>(x + grow*DIM + c*32);
        float stq[32];
        #pragma unroll
        for (int q=0;q<8;q++){
            float4 qv = qw[q];
            float4 xv = xr[q];
            stq[4*q+0] = __fadd_rn(xv.x, __fsub_rn(qv.x, xv.x));
            stq[4*q+1] = __fadd_rn(xv.y, __fsub_rn(qv.y, xv.y));
            stq[4*q+2] = __fadd_rn(xv.z, __fsub_rn(qv.z, xv.z));
            stq[4*q+3] = __fadd_rn(xv.w, __fsub_rn(qv.w, xv.w));
        }
        // out+1 is 4B-aligned: 3 scalars, 7 float4, 1 scalar per 32-chunk
        float* og = out + 1 + grow*DIM + c*32;
        og[0]=stq[0]; og[1]=stq[1]; og[2]=stq[2];
        float4* ov = reinterpret_cast<float4*>(og + 3);
        #pragma unroll
        for (int q=0;q<7;q++){
            float4 r;
            r.x=stq[3+4*q]; r.y=stq[4+4*q]; r.z=stq[5+4*q]; r.w=stq[6+4*q];
            ov[q] = r;
        }
        og[31]=stq[31];
    }
}

extern "C" void kernel_launch(void* const* d_in, const int* in_sizes, int n_in,
                              void* d_out, int out_size)
{
    const float* x  = (const float*)d_in[0];
    const float* wt = (const float*)d_in[1];
    float* out = (float*)d_out;

    cudaFuncSetAttribute(vq_main, cudaFuncAttributeMaxDynamicSharedMemorySize, SMEMSZ);

    vq_prep<<<KC/BT, BT>>>(wt);
    vq_main<<<NROWS/RWS, BT, SMEMSZ>>>(x, wt, out);
}